// round 13
// baseline (speedup 1.0000x reference)
#include <cuda_runtime.h>
#include <cuda_bf16.h>
#include <cuda_fp16.h>
#include <cstdint>
#include <math.h>

#define NN 50000
#define EE 800000
#define GD 256
#define H1D 128
#define RR 8
#define DD 256
#define W0 1152   // (R+1)*H1
#define W1 1024   // 4*D
#define K0B 768   // B-side split K for GEMM0 (3 groups of 256)
#define K1B 384   // B-side split K for GEMM1 (3 groups of 128)
#define K0A 512   // A-side storage: [hi(256)|lo(256)]
#define K1A 256   // A-side storage: [hi(128)|lo(128)]
#define NBLK 196  // ceil(NN/256)

// ---------------- device scratch ----------------
__device__ __align__(128) __nv_bfloat16 g_Abf0[(size_t)NN * K0A];   // 51.2 MB
__device__ __align__(128) __nv_bfloat16 g_Abf1[(size_t)NN * K1A];   // 25.6 MB
__device__ __align__(128) __nv_bfloat16 g_Bt0[(size_t)W0 * K0B];    // B^T: [n][k]
__device__ __align__(128) __nv_bfloat16 g_Bt1[(size_t)W1 * K1B];
__device__ float g_bqkvs[W1];                    // reordered [k|v|q|skip]
__device__ __align__(128) __half g_Y0[(size_t)NN * W0];             // 115.2 MB (fp16)
__device__ __align__(128) __half g_kv[(size_t)NN * 512];            // 51.2 MB (k|v, fp16)
__device__ __align__(128) float g_qs[(size_t)NN * 512];             // 102.4 MB (q|skip)
__device__ int   g_cnt[RR * NN];
__device__ int   g_indeg[NN];
__device__ int   g_rowstart[NN + 1];
__device__ int   g_cursor[NN];
__device__ int   g_srcrel[EE];                  // src | (rel<<24), CSR order
__device__ float g_ew[EE];                      // 1/cnt[rel,dst], CSR order
__device__ int   g_blocksum[NBLK];
__device__ int   g_blockoff[NBLK];
__device__ float g_bnsum[DD];
__device__ float g_bnsumsq[DD];
__device__ float g_scale[DD];
__device__ float g_shift[DD];

// ---------------- helpers ----------------
__device__ __forceinline__ uint32_t smem_u32(const void* p) {
    uint32_t a;
    asm("{ .reg .u64 t; cvta.to.shared.u64 t, %1; cvt.u32.u64 %0, t; }" : "=r"(a) : "l"(p));
    return a;
}
__device__ __forceinline__ void cp16(uint32_t s, const void* g) {
    asm volatile("cp.async.cg.shared.global [%0], [%1], 16;" :: "r"(s), "l"(g));
}
#define CP_COMMIT() asm volatile("cp.async.commit_group;" ::: "memory")
#define CP_WAIT0()  asm volatile("cp.async.wait_group 0;" ::: "memory")
#define CP_WAIT1()  asm volatile("cp.async.wait_group 1;" ::: "memory")

__device__ __forceinline__ void ldsm4(uint32_t& r0, uint32_t& r1, uint32_t& r2, uint32_t& r3,
                                      uint32_t a) {
    asm volatile("ldmatrix.sync.aligned.m8n8.x4.shared.b16 {%0,%1,%2,%3}, [%4];"
                 : "=r"(r0), "=r"(r1), "=r"(r2), "=r"(r3) : "r"(a));
}
__device__ __forceinline__ void mma16816(float* c, uint32_t a0, uint32_t a1, uint32_t a2,
                                         uint32_t a3, uint32_t b0, uint32_t b1) {
    asm volatile("mma.sync.aligned.m16n8k16.row.col.f32.bf16.bf16.f32 "
                 "{%0,%1,%2,%3}, {%4,%5,%6,%7}, {%8,%9}, {%0,%1,%2,%3};"
                 : "+f"(c[0]), "+f"(c[1]), "+f"(c[2]), "+f"(c[3])
                 : "r"(a0), "r"(a1), "r"(a2), "r"(a3), "r"(b0), "r"(b1));
}
__device__ __forceinline__ void split_bf(float v, __nv_bfloat16& h, __nv_bfloat16& l) {
    h = __float2bfloat16_rn(v);
    l = __float2bfloat16_rn(v - __bfloat162float(h));
}

// ---------------- small setup kernels ----------------
__global__ void gnn_zero_kernel() {
    int i = blockIdx.x * blockDim.x + threadIdx.x;
    int stride = gridDim.x * blockDim.x;
    for (int j = i; j < RR * NN; j += stride) g_cnt[j] = 0;
    for (int j = i; j < NN; j += stride) { g_indeg[j] = 0; g_cursor[j] = 0; }
    for (int j = i; j < DD; j += stride) { g_bnsum[j] = 0.f; g_bnsumsq[j] = 0.f; }
}

// B matrices: 3 K-groups [Bhi (pairs Ahi) | Bhi (pairs Alo) | Blo (pairs Ahi)]
__global__ void gnn_pack_kernel(const float* __restrict__ Wrel, const float* __restrict__ Wroot,
                                const float* __restrict__ Wq, const float* __restrict__ Wk,
                                const float* __restrict__ Wv, const float* __restrict__ Ws,
                                const float* __restrict__ bq, const float* __restrict__ bk,
                                const float* __restrict__ bv, const float* __restrict__ bs) {
    int i = blockIdx.x * blockDim.x + threadIdx.x;
    int stride = gridDim.x * blockDim.x;
    for (int j = i; j < GD * W0; j += stride) {
        int k = j / W0, c = j % W0;
        float v;
        if (c < 1024) { int r = c >> 7, h = c & 127; v = Wrel[((size_t)r * GD + k) * H1D + h]; }
        else          { v = Wroot[k * H1D + (c - 1024)]; }
        __nv_bfloat16 h16, l16; split_bf(v, h16, l16);
        size_t b = (size_t)c * K0B;
        g_Bt0[b + k] = h16;
        g_Bt0[b + 256 + k] = h16;
        g_Bt0[b + 512 + k] = l16;
    }
    // GEMM1 column order: [k | v | q | skip]
    for (int j = i; j < H1D * W1; j += stride) {
        int k = j / W1, c = j % W1;
        int seg = c >> 8, cc = c & 255;
        const float* W = (seg == 0) ? Wk : (seg == 1) ? Wv : (seg == 2) ? Wq : Ws;
        float v = W[k * DD + cc];
        __nv_bfloat16 h16, l16; split_bf(v, h16, l16);
        size_t b = (size_t)c * K1B;
        g_Bt1[b + k] = h16;
        g_Bt1[b + 128 + k] = h16;
        g_Bt1[b + 256 + k] = l16;
    }
    for (int j = i; j < W1; j += stride) {
        int seg = j >> 8, cc = j & 255;
        const float* b = (seg == 0) ? bk : (seg == 1) ? bv : (seg == 2) ? bq : bs;
        g_bqkvs[j] = b[cc];
    }
}

__global__ void gnn_convx_kernel(const float* __restrict__ x) {
    int idx = blockIdx.x * blockDim.x + threadIdx.x;
    if (idx >= NN * GD) return;
    int row = idx >> 8, col = idx & 255;
    __nv_bfloat16 h, l; split_bf(x[idx], h, l);
    size_t b = (size_t)row * K0A;
    g_Abf0[b + col] = h;
    g_Abf0[b + 256 + col] = l;
}

// ---------------- counting + parallel scan + CSR fill ----------------
__global__ void gnn_count_kernel(const int* __restrict__ ei, const int* __restrict__ et) {
    int e = blockIdx.x * blockDim.x + threadIdx.x;
    if (e >= EE) return;
    int d = ei[EE + e];
    int r = et[e];
    atomicAdd(&g_cnt[r * NN + d], 1);
    atomicAdd(&g_indeg[d], 1);
}

__global__ void gnn_scanA_kernel() {
    int i = blockIdx.x * 256 + threadIdx.x;
    int v = (i < NN) ? g_indeg[i] : 0;
    __shared__ int ws[8];
    int lane = threadIdx.x & 31, wid = threadIdx.x >> 5;
    #pragma unroll
    for (int o = 16; o > 0; o >>= 1) v += __shfl_xor_sync(0xffffffffu, v, o);
    if (lane == 0) ws[wid] = v;
    __syncthreads();
    if (threadIdx.x == 0) {
        int s = 0;
        #pragma unroll
        for (int w = 0; w < 8; w++) s += ws[w];
        g_blocksum[blockIdx.x] = s;
    }
}

__global__ void gnn_scanB_kernel() {
    __shared__ int tmp[256];
    int t = threadIdx.x;
    int v = (t < NBLK) ? g_blocksum[t] : 0;
    tmp[t] = v; __syncthreads();
    for (int off = 1; off < 256; off <<= 1) {
        int a = (t >= off) ? tmp[t - off] : 0;
        __syncthreads();
        tmp[t] += a;
        __syncthreads();
    }
    if (t < NBLK) g_blockoff[t] = tmp[t] - v;
    if (t == 0) g_rowstart[0] = 0;
}

__global__ void gnn_scanC_kernel() {
    int i = blockIdx.x * 256 + threadIdx.x;
    int lane = threadIdx.x & 31, wid = threadIdx.x >> 5;
    int v = (i < NN) ? g_indeg[i] : 0;
    int x = v;
    #pragma unroll
    for (int o = 1; o < 32; o <<= 1) {
        int y = __shfl_up_sync(0xffffffffu, x, o);
        if (lane >= o) x += y;
    }
    __shared__ int wsum[8], woff[8];
    if (lane == 31) wsum[wid] = x;
    __syncthreads();
    if (threadIdx.x == 0) {
        int s = 0;
        #pragma unroll
        for (int w = 0; w < 8; w++) { woff[w] = s; s += wsum[w]; }
    }
    __syncthreads();
    int incl = x + woff[wid] + g_blockoff[blockIdx.x];
    if (i < NN) g_rowstart[i + 1] = incl;
}

__global__ void gnn_fill_kernel(const int* __restrict__ ei, const int* __restrict__ et) {
    int e = blockIdx.x * blockDim.x + threadIdx.x;
    if (e >= EE) return;
    int s = ei[e];
    int d = ei[EE + e];
    int r = et[e];
    int pos = g_rowstart[d] + atomicAdd(&g_cursor[d], 1);
    g_srcrel[pos] = s | (r << 24);
    g_ew[pos] = 1.f / (float)g_cnt[r * NN + d];
}

// ---------------- bf16 HMMA GEMM: 128x128x64 CTA stages, 3-stage cp.async ----------------
// MODE 0: 4 warps, 64x64 warp tile (measured faster for the long-K GEMM).
// MODE 1: 8 warps, 64x32 warp tile (measured faster for the short-K GEMM).
// Smem pitch = 72 bf16 (144B): ldmatrix 8-row group starts at banks 4r mod 32 -> distinct.
#define SM_PITCH 72
#define A_SM_BYTES (128 * SM_PITCH * 2)      // 18432
#define STG_BYTES  (2 * A_SM_BYTES)          // 36864
#define GEMM_SMEM  (3 * STG_BYTES)           // 110592

template <int MODE>
__global__ void __launch_bounds__((MODE == 0) ? 128 : 256, 2) hmma_gemm_kernel() {
    constexpr int KB = (MODE == 0) ? K0B : K1B;
    constexpr int KA = (MODE == 0) ? K0A : K1A;
    constexpr int SC = KB / 64;              // 12 or 6 stages
    constexpr int TH = KA / 64;              // stages >= TH wrap to A hi region
    constexpr int NC = (MODE == 0) ? W0 : W1;
    constexpr int THREADS = (MODE == 0) ? 128 : 256;
    constexpr int NF = (MODE == 0) ? 8 : 4;         // B 8-col fragments per warp
    constexpr int WNSPAN = (MODE == 0) ? 64 : 32;   // warp-tile N width
    const __nv_bfloat16* __restrict__ A = (MODE == 0) ? g_Abf0 : g_Abf1;
    const __nv_bfloat16* __restrict__ B = (MODE == 0) ? g_Bt0 : g_Bt1;

    extern __shared__ __align__(16) char smem[];
    uint32_t sb = smem_u32(smem);
    int tid = threadIdx.x;
    int lane = tid & 31, wid = tid >> 5;
    int wm = (MODE == 0) ? (wid >> 1) : (wid >> 2);
    int wn = (MODE == 0) ? (wid & 1) : (wid & 3);
    int m0 = blockIdx.y * 128;
    int n0 = blockIdx.x * 128;

    int a_row = wm * 64 + (lane & 7) + ((lane >> 3) & 1) * 8;
    int a_k8  = (lane >= 16) ? 8 : 0;
    int b_row = wn * WNSPAN + (lane & 7) + ((lane >= 16) ? 8 : 0);
    int b_k8  = ((lane >> 3) & 1) * 8;

    float acc[4][NF][4];
    #pragma unroll
    for (int i = 0; i < 4; i++)
        #pragma unroll
        for (int j = 0; j < NF; j++)
            #pragma unroll
            for (int k = 0; k < 4; k++) acc[i][j][k] = 0.f;

    auto load_stage = [&](int sc, int st) {
        int asc = (sc < TH) ? sc : sc - TH;
        uint32_t base = sb + st * STG_BYTES;
        #pragma unroll
        for (int i = 0; i < 1024 / THREADS; i++) {
            int idx = tid + i * THREADS;
            int r = idx >> 3, ch = idx & 7;
            int row = m0 + r; if (row >= NN) row = NN - 1;
            cp16(base + r * (SM_PITCH * 2) + ch * 16,
                 A + (size_t)row * KA + asc * 64 + ch * 8);
        }
        #pragma unroll
        for (int i = 0; i < 1024 / THREADS; i++) {
            int idx = tid + i * THREADS;
            int r = idx >> 3, ch = idx & 7;
            cp16(base + A_SM_BYTES + r * (SM_PITCH * 2) + ch * 16,
                 B + (size_t)(n0 + r) * KB + sc * 64 + ch * 8);
        }
        CP_COMMIT();
    };

    auto compute_stage = [&](int st) {
        uint32_t aoff = sb + st * STG_BYTES;
        uint32_t boff = aoff + A_SM_BYTES;
        #pragma unroll
        for (int kk = 0; kk < 4; kk++) {
            uint32_t af[4][4];
            #pragma unroll
            for (int mf = 0; mf < 4; mf++)
                ldsm4(af[mf][0], af[mf][1], af[mf][2], af[mf][3],
                      aoff + (a_row + mf * 16) * (SM_PITCH * 2) + (kk * 16 + a_k8) * 2);
            uint32_t bf[NF][2];
            #pragma unroll
            for (int jp = 0; jp < NF / 2; jp++) {
                uint32_t r0, r1, r2, r3;
                ldsm4(r0, r1, r2, r3,
                      boff + (b_row + jp * 16) * (SM_PITCH * 2) + (kk * 16 + b_k8) * 2);
                bf[jp * 2 + 0][0] = r0; bf[jp * 2 + 0][1] = r1;
                bf[jp * 2 + 1][0] = r2; bf[jp * 2 + 1][1] = r3;
            }
            #pragma unroll
            for (int mf = 0; mf < 4; mf++)
                #pragma unroll
                for (int nf = 0; nf < NF; nf++)
                    mma16816(acc[mf][nf], af[mf][0], af[mf][1], af[mf][2], af[mf][3],
                             bf[nf][0], bf[nf][1]);
        }
    };

    load_stage(0, 0);
    load_stage(1, 1);
    for (int sc = 0; sc < SC; sc++) {
        if (sc == SC - 1) CP_WAIT0(); else CP_WAIT1();
        __syncthreads();
        if (sc + 2 < SC) load_stage(sc + 2, (sc + 2) % 3);
        compute_stage(sc % 3);
    }

    // epilogue
    int gm = m0 + wm * 64 + (lane >> 2);
    int gn0 = n0 + wn * WNSPAN + (lane & 3) * 2;
    #pragma unroll
    for (int mf = 0; mf < 4; mf++) {
        int row = gm + mf * 16;
        #pragma unroll
        for (int nf = 0; nf < NF; nf++) {
            int col = gn0 + nf * 8;
            float c0 = acc[mf][nf][0], c1 = acc[mf][nf][1];
            float c2 = acc[mf][nf][2], c3 = acc[mf][nf][3];
            if (MODE == 0) {
                __half2 h01 = __floats2half2_rn(c0, c1);
                __half2 h23 = __floats2half2_rn(c2, c3);
                if (row < NN)     *(__half2*)(g_Y0 + (size_t)row * NC + col)       = h01;
                if (row + 8 < NN) *(__half2*)(g_Y0 + (size_t)(row + 8) * NC + col) = h23;
            } else {
                float b0 = g_bqkvs[col], b1 = g_bqkvs[col + 1];
                c0 += b0; c1 += b1; c2 += b0; c3 += b1;
                if (col < 512) {
                    __half2 h01 = __floats2half2_rn(c0, c1);
                    __half2 h23 = __floats2half2_rn(c2, c3);
                    if (row < NN)     *(__half2*)(g_kv + (size_t)row * 512 + col)       = h01;
                    if (row + 8 < NN) *(__half2*)(g_kv + (size_t)(row + 8) * 512 + col) = h23;
                } else {
                    float* dst = g_qs + (col - 512);
                    if (row < NN)     *(float2*)(dst + (size_t)row * 512)       = make_float2(c0, c1);
                    if (row + 8 < NN) *(float2*)(dst + (size_t)(row + 8) * 512) = make_float2(c2, c3);
                }
            }
        }
    }
}

// ---------------- RGCN gather: warp per dst, 1-deep load pipeline, fused bf16-split ----------------
__global__ void gnn_rgcn_gather_kernel(const float* __restrict__ b_rgcn) {
    int w = (int)((blockIdx.x * (size_t)blockDim.x + threadIdx.x) >> 5);
    if (w >= NN) return;
    int lane = threadIdx.x & 31;
    int h0 = lane * 4;
    float ax = 0.f, ay = 0.f, az = 0.f, aw = 0.f;
    int beg = g_rowstart[w], end = g_rowstart[w + 1];
    __half2 y0, y1;
    float wgt = 0.f;
    int sr_next = 0;
    if (beg < end) {
        int sr0 = g_srcrel[beg];
        wgt = g_ew[beg];
        const __half2* yp = (const __half2*)(g_Y0 + (size_t)(sr0 & 0xFFFFFF) * W0
                                             + ((sr0 >> 24) << 7) + h0);
        y0 = yp[0]; y1 = yp[1];
        if (beg + 1 < end) sr_next = g_srcrel[beg + 1];
    }
    for (int j = beg; j < end; j++) {
        __half2 cy0 = y0, cy1 = y1;
        float cwg = wgt;
        if (j + 1 < end) {
            wgt = g_ew[j + 1];
            const __half2* yp = (const __half2*)(g_Y0 + (size_t)(sr_next & 0xFFFFFF) * W0
                                                 + ((sr_next >> 24) << 7) + h0);
            y0 = yp[0]; y1 = yp[1];
            if (j + 2 < end) sr_next = g_srcrel[j + 2];
        }
        float2 f0 = __half22float2(cy0);
        float2 f1 = __half22float2(cy1);
        ax += cwg * f0.x; ay += cwg * f0.y; az += cwg * f1.x; aw += cwg * f1.y;
    }
    const __half2* rp = (const __half2*)(g_Y0 + (size_t)w * W0 + 1024 + h0);
    float2 r0 = __half22float2(rp[0]);
    float2 r1 = __half22float2(rp[1]);
    float4 bb = *(const float4*)(b_rgcn + h0);
    float o[4];
    o[0] = ax + r0.x + bb.x;
    o[1] = ay + r0.y + bb.y;
    o[2] = az + r1.x + bb.z;
    o[3] = aw + r1.y + bb.w;
    size_t base = (size_t)w * K1A;
    #pragma unroll
    for (int i = 0; i < 4; i++) {
        __nv_bfloat16 h, l; split_bf(o[i], h, l);
        g_Abf1[base + h0 + i] = h;
        g_Abf1[base + 128 + h0 + i] = l;
    }
}

// ---------------- attention: warp per dst, 1-deep K/V pipeline, online softmax ----------------
__global__ void __launch_bounds__(256) gnn_attn_kernel(float* __restrict__ out) {
    __shared__ float s_sum[DD], s_sq[DD];
    int tid = threadIdx.x;
    s_sum[tid] = 0.f; s_sq[tid] = 0.f;
    __syncthreads();

    int w = blockIdx.x * 8 + (tid >> 5);     // grid = NN/8 exactly
    int lane = tid & 31;
    int d0 = lane * 8;
    const float* qrow = g_qs + (size_t)w * 512;
    float q8[8], o8[8];
    *(float4*)&q8[0] = *(const float4*)(qrow + d0);
    *(float4*)&q8[4] = *(const float4*)(qrow + d0 + 4);
    #pragma unroll
    for (int i = 0; i < 8; i++) o8[i] = 0.f;
    float m = -3.0e38f, den = 0.f;
    int beg = g_rowstart[w], end = g_rowstart[w + 1];
    uint4 ku, vu;
    int sr_next = 0;
    if (beg < end) {
        int sr0 = g_srcrel[beg];
        const __half* kvrow = g_kv + (size_t)(sr0 & 0xFFFFFF) * 512;
        ku = *(const uint4*)(kvrow + d0);
        vu = *(const uint4*)(kvrow + 256 + d0);
        if (beg + 1 < end) sr_next = g_srcrel[beg + 1];
    }
    for (int j = beg; j < end; j++) {
        uint4 cku = ku, cvu = vu;
        if (j + 1 < end) {
            const __half* kvrow = g_kv + (size_t)(sr_next & 0xFFFFFF) * 512;
            ku = *(const uint4*)(kvrow + d0);
            vu = *(const uint4*)(kvrow + 256 + d0);
            if (j + 2 < end) sr_next = g_srcrel[j + 2];
        }
        float2 k0 = __half22float2(*(__half2*)&cku.x);
        float2 k1 = __half22float2(*(__half2*)&cku.y);
        float2 k2 = __half22float2(*(__half2*)&cku.z);
        float2 k3 = __half22float2(*(__half2*)&cku.w);
        float part = q8[0] * k0.x + q8[1] * k0.y + q8[2] * k1.x + q8[3] * k1.y
                   + q8[4] * k2.x + q8[5] * k2.y + q8[6] * k3.x + q8[7] * k3.y;
        part += __shfl_xor_sync(0xffffffffu, part, 1);
        part += __shfl_xor_sync(0xffffffffu, part, 2);
        part += __shfl_xor_sync(0xffffffffu, part, 4);
        float logit = part * 0.125f;
        float nm = fmaxf(m, logit);
        float corr = __expf(m - nm);
        float p = __expf(logit - nm);
        float2 v0 = __half22float2(*(__half2*)&cvu.x);
        float2 v1 = __half22float2(*(__half2*)&cvu.y);
        float2 v2 = __half22float2(*(__half2*)&cvu.z);
        float2 v3 = __half22float2(*(__half2*)&cvu.w);
        den = den * corr + p;
        o8[0] = o8[0] * corr + p * v0.x;
        o8[1] = o8[1] * corr + p * v0.y;
        o8[2] = o8[2] * corr + p * v1.x;
        o8[3] = o8[3] * corr + p * v1.y;
        o8[4] = o8[4] * corr + p * v2.x;
        o8[5] = o8[5] * corr + p * v2.y;
        o8[6] = o8[6] * corr + p * v3.x;
        o8[7] = o8[7] * corr + p * v3.y;
        m = nm;
    }
    float inv = (den > 0.f) ? 1.f / den : 0.f;
    float sk8[8];
    *(float4*)&sk8[0] = *(const float4*)(qrow + 256 + d0);
    *(float4*)&sk8[4] = *(const float4*)(qrow + 256 + d0 + 4);
    float r8[8];
    #pragma unroll
    for (int i = 0; i < 8; i++) r8[i] = o8[i] * inv + sk8[i];
    float* orow = out + (size_t)w * DD + d0;
    *(float4*)(orow)     = make_float4(r8[0], r8[1], r8[2], r8[3]);
    *(float4*)(orow + 4) = make_float4(r8[4], r8[5], r8[6], r8[7]);
    // BN partials
    #pragma unroll
    for (int i = 0; i < 8; i++) {
        atomicAdd(&s_sum[d0 + i], r8[i]);
        atomicAdd(&s_sq[d0 + i], r8[i] * r8[i]);
    }
    __syncthreads();
    atomicAdd(&g_bnsum[tid], s_sum[tid]);
    atomicAdd(&g_bnsumsq[tid], s_sq[tid]);
}

// ---------------- BatchNorm finalize + normalize ----------------
__global__ void gnn_bn_final_kernel(const float* __restrict__ gamma, const float* __restrict__ beta) {
    int d = threadIdx.x;
    float mu = g_bnsum[d] * (1.f / NN);
    float var = g_bnsumsq[d] * (1.f / NN) - mu * mu;
    float rstd = 1.0f / sqrtf(var + 1e-5f);
    float sc = rstd * gamma[d];
    g_scale[d] = sc;
    g_shift[d] = beta[d] - mu * sc;
}

__global__ void gnn_bn_norm_kernel(float* __restrict__ out) {
    int idx = blockIdx.x * blockDim.x + threadIdx.x;
    if (idx >= NN * DD / 4) return;
    int c = (idx * 4) & 255;
    float4 v = *(float4*)(out + (size_t)idx * 4);
    float4 y;
    y.x = v.x * g_scale[c + 0] + g_shift[c + 0];
    y.y = v.y * g_scale[c + 1] + g_shift[c + 1];
    y.z = v.z * g_scale[c + 2] + g_shift[c + 2];
    y.w = v.w * g_scale[c + 3] + g_shift[c + 3];
    y.x = (y.x >= 0.f) ? y.x : 0.01f * y.x;
    y.y = (y.y >= 0.f) ? y.y : 0.01f * y.y;
    y.z = (y.z >= 0.f) ? y.z : 0.01f * y.z;
    y.w = (y.w >= 0.f) ? y.w : 0.01f * y.w;
    *(float4*)(out + (size_t)idx * 4) = y;
}

extern "C" void kernel_launch(void* const* d_in, const int* in_sizes, int n_in,
                              void* d_out, int out_size) {
    const float* x     = (const float*)d_in[0];
    const int*   ei    = (const int*)d_in[2];
    const int*   et    = (const int*)d_in[3];
    const float* Wrel  = (const float*)d_in[4];
    const float* Wroot = (const float*)d_in[5];
    const float* brg   = (const float*)d_in[6];
    const float* Wq    = (const float*)d_in[7];
    const float* bq    = (const float*)d_in[8];
    const float* Wk    = (const float*)d_in[9];
    const float* bk    = (const float*)d_in[10];
    const float* Wv    = (const float*)d_in[11];
    const float* bv    = (const float*)d_in[12];
    const float* Ws    = (const float*)d_in[13];
    const float* bs    = (const float*)d_in[14];
    const float* gamma = (const float*)d_in[15];
    const float* beta  = (const float*)d_in[16];
    float* out = (float*)d_out;

    cudaFuncSetAttribute(hmma_gemm_kernel<0>, cudaFuncAttributeMaxDynamicSharedMemorySize, GEMM_SMEM);
    cudaFuncSetAttribute(hmma_gemm_kernel<1>, cudaFuncAttributeMaxDynamicSharedMemorySize, GEMM_SMEM);

    // Launch order keeps GEMM0 in profiled slot #4.
    gnn_zero_kernel<<<512, 256>>>();
    gnn_pack_kernel<<<512, 256>>>(Wrel, Wroot, Wq, Wk, Wv, Ws, bq, bk, bv, bs);
    gnn_convx_kernel<<<(NN * GD + 255) / 256, 256>>>(x);

    // GEMM0: Y0[N,1152] = split-bf16( X @ [Wrel|Wroot] ), stored fp16 — 4 warps 64x64
    dim3 g0(W0 / 128, (NN + 127) / 128);
    hmma_gemm_kernel<0><<<g0, 128, GEMM_SMEM>>>();

    gnn_count_kernel<<<(EE + 255) / 256, 256>>>(ei, et);
    gnn_scanA_kernel<<<NBLK, 256>>>();
    gnn_scanB_kernel<<<1, 256>>>();
    gnn_scanC_kernel<<<NBLK, 256>>>();
    gnn_fill_kernel<<<(EE + 255) / 256, 256>>>(ei, et);

    gnn_rgcn_gather_kernel<<<(NN * 32 + 255) / 256, 256>>>(brg);

    // GEMM1: [k|v|q|skip] = split-bf16( x1 @ W ) + bias — 8 warps 64x32
    dim3 g1(W1 / 128, (NN + 127) / 128);
    hmma_gemm_kernel<1><<<g1, 256, GEMM_SMEM>>>();

    gnn_attn_kernel<<<NN / 8, 256>>>(out);

    gnn_bn_final_kernel<<<1, 256>>>(gamma, beta);
    gnn_bn_norm_kernel<<<(NN * DD / 4 + 255) / 256, 256>>>(out);
}

// round 14
// speedup vs baseline: 1.1972x; 1.1972x over previous
#include <cuda_runtime.h>
#include <cuda_fp16.h>
#include <cstdint>
#include <math.h>

#define NN 50000
#define EE 800000
#define GD 256
#define H1D 128
#define RR 8
#define DD 256
#define W0 1152   // (R+1)*H1
#define W1 1024   // 4*D
#define K0K 512   // GEMM0 K: A=[ah(256)|al(256)], B=[bh|bh]
#define K1K 256   // GEMM1 K: A=[ah(128)|al(128)], B=[bh|bh]
#define NBLK 196  // ceil(NN/256)

// ---------------- device scratch ----------------
__device__ __align__(128) __half g_Ah0[(size_t)NN * K0K];   // 51.2 MB
__device__ __align__(128) __half g_Ah1[(size_t)NN * K1K];   // 25.6 MB
__device__ __align__(128) __half g_Bt0[(size_t)W0 * K0K];   // B^T: [n][k], bh duplicated
__device__ __align__(128) __half g_Bt1[(size_t)W1 * K1K];
__device__ float g_bqkvs[W1];                    // reordered [k|v|q|skip]
__device__ __align__(128) __half g_Y0[(size_t)NN * W0];     // 115.2 MB (fp16)
__device__ __align__(128) __half g_kv[(size_t)NN * 512];    // 51.2 MB (k|v, fp16)
__device__ __align__(128) float g_qs[(size_t)NN * 512];     // 102.4 MB (q|skip)
__device__ int   g_cnt[RR * NN];
__device__ int   g_indeg[NN];
__device__ int   g_rowstart[NN + 1];
__device__ int   g_cursor[NN];
__device__ int   g_srcrel[EE];                  // src | (rel<<24), CSR order
__device__ float g_ew[EE];                      // 1/cnt[rel,dst], CSR order
__device__ int   g_blocksum[NBLK];
__device__ int   g_blockoff[NBLK];
__device__ float g_bnsum[DD];
__device__ float g_bnsumsq[DD];
__device__ float g_scale[DD];
__device__ float g_shift[DD];

// ---------------- helpers ----------------
__device__ __forceinline__ uint32_t smem_u32(const void* p) {
    uint32_t a;
    asm("{ .reg .u64 t; cvta.to.shared.u64 t, %1; cvt.u32.u64 %0, t; }" : "=r"(a) : "l"(p));
    return a;
}
__device__ __forceinline__ void cp16(uint32_t s, const void* g) {
    asm volatile("cp.async.cg.shared.global [%0], [%1], 16;" :: "r"(s), "l"(g));
}
#define CP_COMMIT() asm volatile("cp.async.commit_group;" ::: "memory")
#define CP_WAIT0()  asm volatile("cp.async.wait_group 0;" ::: "memory")
#define CP_WAIT1()  asm volatile("cp.async.wait_group 1;" ::: "memory")

__device__ __forceinline__ void ldsm4(uint32_t& r0, uint32_t& r1, uint32_t& r2, uint32_t& r3,
                                      uint32_t a) {
    asm volatile("ldmatrix.sync.aligned.m8n8.x4.shared.b16 {%0,%1,%2,%3}, [%4];"
                 : "=r"(r0), "=r"(r1), "=r"(r2), "=r"(r3) : "r"(a));
}
__device__ __forceinline__ void mma16816(float* c, uint32_t a0, uint32_t a1, uint32_t a2,
                                         uint32_t a3, uint32_t b0, uint32_t b1) {
    asm volatile("mma.sync.aligned.m16n8k16.row.col.f32.f16.f16.f32 "
                 "{%0,%1,%2,%3}, {%4,%5,%6,%7}, {%8,%9}, {%0,%1,%2,%3};"
                 : "+f"(c[0]), "+f"(c[1]), "+f"(c[2]), "+f"(c[3])
                 : "r"(a0), "r"(a1), "r"(a2), "r"(a3), "r"(b0), "r"(b1));
}
__device__ __forceinline__ void split_h(float v, __half& h, __half& l) {
    h = __float2half_rn(v);
    l = __float2half_rn(v - __half2float(h));
}

// ---------------- small setup kernels ----------------
__global__ void gnn_zero_kernel() {
    int i = blockIdx.x * blockDim.x + threadIdx.x;
    int stride = gridDim.x * blockDim.x;
    for (int j = i; j < RR * NN; j += stride) g_cnt[j] = 0;
    for (int j = i; j < NN; j += stride) { g_indeg[j] = 0; g_cursor[j] = 0; }
    for (int j = i; j < DD; j += stride) { g_bnsum[j] = 0.f; g_bnsumsq[j] = 0.f; }
}

// B matrices: fp16 bh duplicated in both K-groups (pairs with A hi and A lo)
__global__ void gnn_pack_kernel(const float* __restrict__ Wrel, const float* __restrict__ Wroot,
                                const float* __restrict__ Wq, const float* __restrict__ Wk,
                                const float* __restrict__ Wv, const float* __restrict__ Ws,
                                const float* __restrict__ bq, const float* __restrict__ bk,
                                const float* __restrict__ bv, const float* __restrict__ bs) {
    int i = blockIdx.x * blockDim.x + threadIdx.x;
    int stride = gridDim.x * blockDim.x;
    for (int j = i; j < GD * W0; j += stride) {
        int k = j / W0, c = j % W0;
        float v;
        if (c < 1024) { int r = c >> 7, h = c & 127; v = Wrel[((size_t)r * GD + k) * H1D + h]; }
        else          { v = Wroot[k * H1D + (c - 1024)]; }
        __half h16 = __float2half_rn(v);
        size_t b = (size_t)c * K0K;
        g_Bt0[b + k] = h16;
        g_Bt0[b + 256 + k] = h16;
    }
    // GEMM1 column order: [k | v | q | skip]
    for (int j = i; j < H1D * W1; j += stride) {
        int k = j / W1, c = j % W1;
        int seg = c >> 8, cc = c & 255;
        const float* W = (seg == 0) ? Wk : (seg == 1) ? Wv : (seg == 2) ? Wq : Ws;
        __half h16 = __float2half_rn(W[k * DD + cc]);
        size_t b = (size_t)c * K1K;
        g_Bt1[b + k] = h16;
        g_Bt1[b + 128 + k] = h16;
    }
    for (int j = i; j < W1; j += stride) {
        int seg = j >> 8, cc = j & 255;
        const float* b = (seg == 0) ? bk : (seg == 1) ? bv : (seg == 2) ? bq : bs;
        g_bqkvs[j] = b[cc];
    }
}

__global__ void gnn_convx_kernel(const float* __restrict__ x) {
    int idx = blockIdx.x * blockDim.x + threadIdx.x;
    if (idx >= NN * GD) return;
    int row = idx >> 8, col = idx & 255;
    __half h, l; split_h(x[idx], h, l);
    size_t b = (size_t)row * K0K;
    g_Ah0[b + col] = h;
    g_Ah0[b + 256 + col] = l;
}

// ---------------- counting + parallel scan + CSR fill ----------------
__global__ void gnn_count_kernel(const int* __restrict__ ei, const int* __restrict__ et) {
    int e = blockIdx.x * blockDim.x + threadIdx.x;
    if (e >= EE) return;
    int d = ei[EE + e];
    int r = et[e];
    atomicAdd(&g_cnt[r * NN + d], 1);
    atomicAdd(&g_indeg[d], 1);
}

__global__ void gnn_scanA_kernel() {
    int i = blockIdx.x * 256 + threadIdx.x;
    int v = (i < NN) ? g_indeg[i] : 0;
    __shared__ int ws[8];
    int lane = threadIdx.x & 31, wid = threadIdx.x >> 5;
    #pragma unroll
    for (int o = 16; o > 0; o >>= 1) v += __shfl_xor_sync(0xffffffffu, v, o);
    if (lane == 0) ws[wid] = v;
    __syncthreads();
    if (threadIdx.x == 0) {
        int s = 0;
        #pragma unroll
        for (int w = 0; w < 8; w++) s += ws[w];
        g_blocksum[blockIdx.x] = s;
    }
}

__global__ void gnn_scanB_kernel() {
    __shared__ int tmp[256];
    int t = threadIdx.x;
    int v = (t < NBLK) ? g_blocksum[t] : 0;
    tmp[t] = v; __syncthreads();
    for (int off = 1; off < 256; off <<= 1) {
        int a = (t >= off) ? tmp[t - off] : 0;
        __syncthreads();
        tmp[t] += a;
        __syncthreads();
    }
    if (t < NBLK) g_blockoff[t] = tmp[t] - v;
    if (t == 0) g_rowstart[0] = 0;
}

__global__ void gnn_scanC_kernel() {
    int i = blockIdx.x * 256 + threadIdx.x;
    int lane = threadIdx.x & 31, wid = threadIdx.x >> 5;
    int v = (i < NN) ? g_indeg[i] : 0;
    int x = v;
    #pragma unroll
    for (int o = 1; o < 32; o <<= 1) {
        int y = __shfl_up_sync(0xffffffffu, x, o);
        if (lane >= o) x += y;
    }
    __shared__ int wsum[8], woff[8];
    if (lane == 31) wsum[wid] = x;
    __syncthreads();
    if (threadIdx.x == 0) {
        int s = 0;
        #pragma unroll
        for (int w = 0; w < 8; w++) { woff[w] = s; s += wsum[w]; }
    }
    __syncthreads();
    int incl = x + woff[wid] + g_blockoff[blockIdx.x];
    if (i < NN) g_rowstart[i + 1] = incl;
}

__global__ void gnn_fill_kernel(const int* __restrict__ ei, const int* __restrict__ et) {
    int e = blockIdx.x * blockDim.x + threadIdx.x;
    if (e >= EE) return;
    int s = ei[e];
    int d = ei[EE + e];
    int r = et[e];
    int pos = g_rowstart[d] + atomicAdd(&g_cursor[d], 1);
    g_srcrel[pos] = s | (r << 24);
    g_ew[pos] = 1.f / (float)g_cnt[r * NN + d];
}

// ---------------- fp16 HMMA GEMM: 128x128x64 stages, 8 warps of 64x32, 3-stage cp.async ----------------
// Smem pitch = 72 halves (144B): ldmatrix 8-row group starts at banks 4r mod 32 -> distinct.
// A = [ah|al] exact fp16 pair; B = [bh|bh] duplicated -> result = x (.) bh (B-rounding error only).
#define SM_PITCH 72
#define A_SM_BYTES (128 * SM_PITCH * 2)      // 18432
#define STG_BYTES  (2 * A_SM_BYTES)          // 36864
#define GEMM_SMEM  (3 * STG_BYTES)           // 110592

template <int MODE>
__global__ void __launch_bounds__(256) hmma_gemm_kernel() {
    constexpr int KK = (MODE == 0) ? K0K : K1K;
    constexpr int SC = KK / 64;              // 8 or 4 stages
    constexpr int NC = (MODE == 0) ? W0 : W1;
    const __half* __restrict__ A = (MODE == 0) ? g_Ah0 : g_Ah1;
    const __half* __restrict__ B = (MODE == 0) ? g_Bt0 : g_Bt1;

    extern __shared__ __align__(16) char smem[];
    uint32_t sb = smem_u32(smem);
    int tid = threadIdx.x;
    int lane = tid & 31, wid = tid >> 5;
    int wm = wid >> 2, wn = wid & 3;          // 2 x 4 warps; warp tile 64 x 32
    int m0 = blockIdx.y * 128;
    int n0 = blockIdx.x * 128;

    int a_row = wm * 64 + (lane & 7) + ((lane >> 3) & 1) * 8;
    int a_k8  = (lane >= 16) ? 8 : 0;
    int b_row = wn * 32 + (lane & 7) + ((lane >= 16) ? 8 : 0);
    int b_k8  = ((lane >> 3) & 1) * 8;

    float acc[4][4][4];
    #pragma unroll
    for (int i = 0; i < 4; i++)
        #pragma unroll
        for (int j = 0; j < 4; j++)
            #pragma unroll
            for (int k = 0; k < 4; k++) acc[i][j][k] = 0.f;

    auto load_stage = [&](int sc, int st) {
        uint32_t base = sb + st * STG_BYTES;
        #pragma unroll
        for (int i = 0; i < 4; i++) {
            int idx = tid + i * 256;
            int r = idx >> 3, ch = idx & 7;
            int row = m0 + r; if (row >= NN) row = NN - 1;
            cp16(base + r * (SM_PITCH * 2) + ch * 16,
                 A + (size_t)row * KK + sc * 64 + ch * 8);
        }
        #pragma unroll
        for (int i = 0; i < 4; i++) {
            int idx = tid + i * 256;
            int r = idx >> 3, ch = idx & 7;
            cp16(base + A_SM_BYTES + r * (SM_PITCH * 2) + ch * 16,
                 B + (size_t)(n0 + r) * KK + sc * 64 + ch * 8);
        }
        CP_COMMIT();
    };

    auto compute_stage = [&](int st) {
        uint32_t aoff = sb + st * STG_BYTES;
        uint32_t boff = aoff + A_SM_BYTES;
        #pragma unroll
        for (int kk = 0; kk < 4; kk++) {
            uint32_t af[4][4];
            #pragma unroll
            for (int mf = 0; mf < 4; mf++)
                ldsm4(af[mf][0], af[mf][1], af[mf][2], af[mf][3],
                      aoff + (a_row + mf * 16) * (SM_PITCH * 2) + (kk * 16 + a_k8) * 2);
            uint32_t bf[4][2];
            #pragma unroll
            for (int jp = 0; jp < 2; jp++) {
                uint32_t r0, r1, r2, r3;
                ldsm4(r0, r1, r2, r3,
                      boff + (b_row + jp * 16) * (SM_PITCH * 2) + (kk * 16 + b_k8) * 2);
                bf[jp * 2 + 0][0] = r0; bf[jp * 2 + 0][1] = r1;
                bf[jp * 2 + 1][0] = r2; bf[jp * 2 + 1][1] = r3;
            }
            #pragma unroll
            for (int mf = 0; mf < 4; mf++)
                #pragma unroll
                for (int nf = 0; nf < 4; nf++)
                    mma16816(acc[mf][nf], af[mf][0], af[mf][1], af[mf][2], af[mf][3],
                             bf[nf][0], bf[nf][1]);
        }
    };

    load_stage(0, 0);
    load_stage(1, 1);
    for (int sc = 0; sc < SC; sc++) {
        if (sc == SC - 1) CP_WAIT0(); else CP_WAIT1();
        __syncthreads();
        if (sc + 2 < SC) load_stage(sc + 2, (sc + 2) % 3);
        compute_stage(sc % 3);
    }

    // epilogue
    int gm = m0 + wm * 64 + (lane >> 2);
    int gn0 = n0 + wn * 32 + (lane & 3) * 2;
    #pragma unroll
    for (int mf = 0; mf < 4; mf++) {
        int row = gm + mf * 16;
        #pragma unroll
        for (int nf = 0; nf < 4; nf++) {
            int col = gn0 + nf * 8;
            float c0 = acc[mf][nf][0], c1 = acc[mf][nf][1];
            float c2 = acc[mf][nf][2], c3 = acc[mf][nf][3];
            if (MODE == 0) {
                __half2 h01 = __floats2half2_rn(c0, c1);
                __half2 h23 = __floats2half2_rn(c2, c3);
                if (row < NN)     *(__half2*)(g_Y0 + (size_t)row * NC + col)       = h01;
                if (row + 8 < NN) *(__half2*)(g_Y0 + (size_t)(row + 8) * NC + col) = h23;
            } else {
                float b0 = g_bqkvs[col], b1 = g_bqkvs[col + 1];
                c0 += b0; c1 += b1; c2 += b0; c3 += b1;
                if (col < 512) {
                    __half2 h01 = __floats2half2_rn(c0, c1);
                    __half2 h23 = __floats2half2_rn(c2, c3);
                    if (row < NN)     *(__half2*)(g_kv + (size_t)row * 512 + col)       = h01;
                    if (row + 8 < NN) *(__half2*)(g_kv + (size_t)(row + 8) * 512 + col) = h23;
                } else {
                    float* dst = g_qs + (col - 512);
                    if (row < NN)     *(float2*)(dst + (size_t)row * 512)       = make_float2(c0, c1);
                    if (row + 8 < NN) *(float2*)(dst + (size_t)(row + 8) * 512) = make_float2(c2, c3);
                }
            }
        }
    }
}

// ---------------- RGCN gather: warp per dst, prefetch, fused fp16-split ----------------
__global__ void gnn_rgcn_gather_kernel(const float* __restrict__ b_rgcn) {
    int w = (int)((blockIdx.x * (size_t)blockDim.x + threadIdx.x) >> 5);
    if (w >= NN) return;
    int lane = threadIdx.x & 31;
    int h0 = lane * 4;
    float ax = 0.f, ay = 0.f, az = 0.f, aw = 0.f;
    int beg = g_rowstart[w], end = g_rowstart[w + 1];
    int sr = (beg < end) ? g_srcrel[beg] : 0;
    float wgt = (beg < end) ? g_ew[beg] : 0.f;
    for (int j = beg; j < end; j++) {
        int s = sr & 0xFFFFFF;
        int r = sr >> 24;
        float wg = wgt;
        if (j + 1 < end) { sr = g_srcrel[j + 1]; wgt = g_ew[j + 1]; }
        const __half2* yp = (const __half2*)(g_Y0 + (size_t)s * W0 + (r << 7) + h0);
        float2 f0 = __half22float2(yp[0]);
        float2 f1 = __half22float2(yp[1]);
        ax += wg * f0.x; ay += wg * f0.y; az += wg * f1.x; aw += wg * f1.y;
    }
    const __half2* rp = (const __half2*)(g_Y0 + (size_t)w * W0 + 1024 + h0);
    float2 r0 = __half22float2(rp[0]);
    float2 r1 = __half22float2(rp[1]);
    float4 bb = *(const float4*)(b_rgcn + h0);
    float o[4];
    o[0] = ax + r0.x + bb.x;
    o[1] = ay + r0.y + bb.y;
    o[2] = az + r1.x + bb.z;
    o[3] = aw + r1.y + bb.w;
    size_t base = (size_t)w * K1K;
    #pragma unroll
    for (int i = 0; i < 4; i++) {
        __half h, l; split_h(o[i], h, l);
        g_Ah1[base + h0 + i] = h;
        g_Ah1[base + 128 + h0 + i] = l;
    }
}

// ---------------- attention: warp per dst, online softmax, fused skip + BN partials ----------------
__global__ void __launch_bounds__(256) gnn_attn_kernel(float* __restrict__ out) {
    __shared__ float s_sum[DD], s_sq[DD];
    int tid = threadIdx.x;
    s_sum[tid] = 0.f; s_sq[tid] = 0.f;
    __syncthreads();

    int w = blockIdx.x * 8 + (tid >> 5);     // grid = NN/8 exactly
    int lane = tid & 31;
    int d0 = lane * 8;
    const float* qrow = g_qs + (size_t)w * 512;
    float q8[8], o8[8];
    *(float4*)&q8[0] = *(const float4*)(qrow + d0);
    *(float4*)&q8[4] = *(const float4*)(qrow + d0 + 4);
    #pragma unroll
    for (int i = 0; i < 8; i++) o8[i] = 0.f;
    float m = -3.0e38f, den = 0.f;
    int beg = g_rowstart[w], end = g_rowstart[w + 1];
    int sr = (beg < end) ? g_srcrel[beg] : 0;
    for (int j = beg; j < end; j++) {
        int s = sr & 0xFFFFFF;
        if (j + 1 < end) sr = g_srcrel[j + 1];
        const __half* kvrow = g_kv + (size_t)s * 512;
        uint4 ku = *(const uint4*)(kvrow + d0);
        uint4 vu = *(const uint4*)(kvrow + 256 + d0);
        float2 k0 = __half22float2(*(__half2*)&ku.x);
        float2 k1 = __half22float2(*(__half2*)&ku.y);
        float2 k2 = __half22float2(*(__half2*)&ku.z);
        float2 k3 = __half22float2(*(__half2*)&ku.w);
        float part = q8[0] * k0.x + q8[1] * k0.y + q8[2] * k1.x + q8[3] * k1.y
                   + q8[4] * k2.x + q8[5] * k2.y + q8[6] * k3.x + q8[7] * k3.y;
        part += __shfl_xor_sync(0xffffffffu, part, 1);
        part += __shfl_xor_sync(0xffffffffu, part, 2);
        part += __shfl_xor_sync(0xffffffffu, part, 4);
        float logit = part * 0.125f;
        float nm = fmaxf(m, logit);
        float corr = __expf(m - nm);
        float p = __expf(logit - nm);
        float2 v0 = __half22float2(*(__half2*)&vu.x);
        float2 v1 = __half22float2(*(__half2*)&vu.y);
        float2 v2 = __half22float2(*(__half2*)&vu.z);
        float2 v3 = __half22float2(*(__half2*)&vu.w);
        den = den * corr + p;
        o8[0] = o8[0] * corr + p * v0.x;
        o8[1] = o8[1] * corr + p * v0.y;
        o8[2] = o8[2] * corr + p * v1.x;
        o8[3] = o8[3] * corr + p * v1.y;
        o8[4] = o8[4] * corr + p * v2.x;
        o8[5] = o8[5] * corr + p * v2.y;
        o8[6] = o8[6] * corr + p * v3.x;
        o8[7] = o8[7] * corr + p * v3.y;
        m = nm;
    }
    float inv = (den > 0.f) ? 1.f / den : 0.f;
    float sk8[8];
    *(float4*)&sk8[0] = *(const float4*)(qrow + 256 + d0);
    *(float4*)&sk8[4] = *(const float4*)(qrow + 256 + d0 + 4);
    float r8[8];
    #pragma unroll
    for (int i = 0; i < 8; i++) r8[i] = o8[i] * inv + sk8[i];
    float* orow = out + (size_t)w * DD + d0;
    *(float4*)(orow)     = make_float4(r8[0], r8[1], r8[2], r8[3]);
    *(float4*)(orow + 4) = make_float4(r8[4], r8[5], r8[6], r8[7]);
    // BN partials
    #pragma unroll
    for (int i = 0; i < 8; i++) {
        atomicAdd(&s_sum[d0 + i], r8[i]);
        atomicAdd(&s_sq[d0 + i], r8[i] * r8[i]);
    }
    __syncthreads();
    atomicAdd(&g_bnsum[tid], s_sum[tid]);
    atomicAdd(&g_bnsumsq[tid], s_sq[tid]);
}

// ---------------- BatchNorm finalize + normalize ----------------
__global__ void gnn_bn_final_kernel(const float* __restrict__ gamma, const float* __restrict__ beta) {
    int d = threadIdx.x;
    float mu = g_bnsum[d] * (1.f / NN);
    float var = g_bnsumsq[d] * (1.f / NN) - mu * mu;
    float rstd = 1.0f / sqrtf(var + 1e-5f);
    float sc = rstd * gamma[d];
    g_scale[d] = sc;
    g_shift[d] = beta[d] - mu * sc;
}

__global__ void gnn_bn_norm_kernel(float* __restrict__ out) {
    int idx = blockIdx.x * blockDim.x + threadIdx.x;
    if (idx >= NN * DD / 4) return;
    int c = (idx * 4) & 255;
    float4 v = *(float4*)(out + (size_t)idx * 4);
    float4 y;
    y.x = v.x * g_scale[c + 0] + g_shift[c + 0];
    y.y = v.y * g_scale[c + 1] + g_shift[c + 1];
    y.z = v.z * g_scale[c + 2] + g_shift[c + 2];
    y.w = v.w * g_scale[c + 3] + g_shift[c + 3];
    y.x = (y.x >= 0.f) ? y.x : 0.01f * y.x;
    y.y = (y.y >= 0.f) ? y.y : 0.01f * y.y;
    y.z = (y.z >= 0.f) ? y.z : 0.01f * y.z;
    y.w = (y.w >= 0.f) ? y.w : 0.01f * y.w;
    *(float4*)(out + (size_t)idx * 4) = y;
}

extern "C" void kernel_launch(void* const* d_in, const int* in_sizes, int n_in,
                              void* d_out, int out_size) {
    const float* x     = (const float*)d_in[0];
    const int*   ei    = (const int*)d_in[2];
    const int*   et    = (const int*)d_in[3];
    const float* Wrel  = (const float*)d_in[4];
    const float* Wroot = (const float*)d_in[5];
    const float* brg   = (const float*)d_in[6];
    const float* Wq    = (const float*)d_in[7];
    const float* bq    = (const float*)d_in[8];
    const float* Wk    = (const float*)d_in[9];
    const float* bk    = (const float*)d_in[10];
    const float* Wv    = (const float*)d_in[11];
    const float* bv    = (const float*)d_in[12];
    const float* Ws    = (const float*)d_in[13];
    const float* bs    = (const float*)d_in[14];
    const float* gamma = (const float*)d_in[15];
    const float* beta  = (const float*)d_in[16];
    float* out = (float*)d_out;

    cudaFuncSetAttribute(hmma_gemm_kernel<0>, cudaFuncAttributeMaxDynamicSharedMemorySize, GEMM_SMEM);
    cudaFuncSetAttribute(hmma_gemm_kernel<1>, cudaFuncAttributeMaxDynamicSharedMemorySize, GEMM_SMEM);

    // Launch order keeps GEMM0 in profiled slot #4.
    gnn_zero_kernel<<<512, 256>>>();
    gnn_pack_kernel<<<512, 256>>>(Wrel, Wroot, Wq, Wk, Wv, Ws, bq, bk, bv, bs);
    gnn_convx_kernel<<<(NN * GD + 255) / 256, 256>>>(x);

    // GEMM0: Y0[N,1152] = [ah|al] @ [bh|bh]  (K=512), stored fp16
    dim3 g0(W0 / 128, (NN + 127) / 128);
    hmma_gemm_kernel<0><<<g0, 256, GEMM_SMEM>>>();

    gnn_count_kernel<<<(EE + 255) / 256, 256>>>(ei, et);
    gnn_scanA_kernel<<<NBLK, 256>>>();
    gnn_scanB_kernel<<<1, 256>>>();
    gnn_scanC_kernel<<<NBLK, 256>>>();
    gnn_fill_kernel<<<(EE + 255) / 256, 256>>>(ei, et);

    gnn_rgcn_gather_kernel<<<(NN * 32 + 255) / 256, 256>>>(brg);

    // GEMM1: [k|v|q|skip] (K=256) + bias; k|v stored fp16
    dim3 g1(W1 / 128, (NN + 127) / 128);
    hmma_gemm_kernel<1><<<g1, 256, GEMM_SMEM>>>();

    gnn_attn_kernel<<<NN / 8, 256>>>(out);

    gnn_bn_final_kernel<<<1, 256>>>(gamma, beta);
    gnn_bn_norm_kernel<<<(NN * DD / 4 + 255) / 256, 256>>>(out);
}

// round 16
// speedup vs baseline: 1.2155x; 1.0153x over previous
#include <cuda_runtime.h>
#include <cuda_fp16.h>
#include <cstdint>
#include <math.h>

#define NN 50000
#define EE 800000
#define GD 256
#define H1D 128
#define RR 8
#define DD 256
#define W0 1152   // (R+1)*H1
#define W1 1024   // 4*D
#define K0K 512   // GEMM0 K: A=[ah(256)|al(256)], B=[bh|bh]
#define K1K 256   // GEMM1 K: A=[ah(128)|al(128)], B=[bh|bh]
#define NBLK 196  // ceil(NN/256)

// ---------------- device scratch ----------------
__device__ __align__(128) __half g_Ah0[(size_t)NN * K0K];   // 51.2 MB
__device__ __align__(128) __half g_Ah1[(size_t)NN * K1K];   // 25.6 MB
__device__ __align__(128) __half g_Bt0[(size_t)W0 * K0K];   // B^T: [n][k], bh duplicated
__device__ __align__(128) __half g_Bt1[(size_t)W1 * K1K];
__device__ float g_bqkvs[W1];                    // reordered [k|v|q|skip]
__device__ __align__(128) __half g_Y0[(size_t)NN * W0];     // 115.2 MB (fp16)
__device__ __align__(128) __half g_kv[(size_t)NN * 512];    // 51.2 MB (k|v, fp16)
__device__ __align__(128) float g_qs[(size_t)NN * 512];     // 102.4 MB (q|skip)
__device__ int   g_cnt[RR * NN];
__device__ int   g_indeg[NN];
__device__ int   g_rowstart[NN + 1];
__device__ int   g_cursor[NN];
__device__ int   g_srcrel[EE];                  // src | (rel<<24), CSR order
__device__ float g_ew[EE];                      // 1/cnt[rel,dst], CSR order
__device__ int   g_blocksum[NBLK];
__device__ int   g_blockoff[NBLK];
__device__ float g_bnsum[DD];
__device__ float g_bnsumsq[DD];
__device__ float g_scale[DD];
__device__ float g_shift[DD];

// ---------------- helpers ----------------
__device__ __forceinline__ uint32_t smem_u32(const void* p) {
    uint32_t a;
    asm("{ .reg .u64 t; cvta.to.shared.u64 t, %1; cvt.u32.u64 %0, t; }" : "=r"(a) : "l"(p));
    return a;
}
__device__ __forceinline__ void cp16(uint32_t s, const void* g) {
    asm volatile("cp.async.cg.shared.global [%0], [%1], 16;" :: "r"(s), "l"(g));
}
#define CP_COMMIT() asm volatile("cp.async.commit_group;" ::: "memory")
#define CP_WAIT0()  asm volatile("cp.async.wait_group 0;" ::: "memory")
#define CP_WAIT1()  asm volatile("cp.async.wait_group 1;" ::: "memory")

__device__ __forceinline__ void ldsm4(uint32_t& r0, uint32_t& r1, uint32_t& r2, uint32_t& r3,
                                      uint32_t a) {
    asm volatile("ldmatrix.sync.aligned.m8n8.x4.shared.b16 {%0,%1,%2,%3}, [%4];"
                 : "=r"(r0), "=r"(r1), "=r"(r2), "=r"(r3) : "r"(a));
}
__device__ __forceinline__ void mma16816(float* c, uint32_t a0, uint32_t a1, uint32_t a2,
                                         uint32_t a3, uint32_t b0, uint32_t b1) {
    asm volatile("mma.sync.aligned.m16n8k16.row.col.f32.f16.f16.f32 "
                 "{%0,%1,%2,%3}, {%4,%5,%6,%7}, {%8,%9}, {%0,%1,%2,%3};"
                 : "+f"(c[0]), "+f"(c[1]), "+f"(c[2]), "+f"(c[3])
                 : "r"(a0), "r"(a1), "r"(a2), "r"(a3), "r"(b0), "r"(b1));
}
__device__ __forceinline__ void split_h(float v, __half& h, __half& l) {
    h = __float2half_rn(v);
    l = __float2half_rn(v - __half2float(h));
}

// ---------------- small setup kernels ----------------
__global__ void gnn_zero_kernel() {
    int i = blockIdx.x * blockDim.x + threadIdx.x;
    int stride = gridDim.x * blockDim.x;
    for (int j = i; j < RR * NN; j += stride) g_cnt[j] = 0;
    for (int j = i; j < NN; j += stride) { g_indeg[j] = 0; g_cursor[j] = 0; }
    for (int j = i; j < DD; j += stride) { g_bnsum[j] = 0.f; g_bnsumsq[j] = 0.f; }
}

// B matrices: fp16 bh duplicated in both K-groups (pairs with A hi and A lo)
__global__ void gnn_pack_kernel(const float* __restrict__ Wrel, const float* __restrict__ Wroot,
                                const float* __restrict__ Wq, const float* __restrict__ Wk,
                                const float* __restrict__ Wv, const float* __restrict__ Ws,
                                const float* __restrict__ bq, const float* __restrict__ bk,
                                const float* __restrict__ bv, const float* __restrict__ bs) {
    int i = blockIdx.x * blockDim.x + threadIdx.x;
    int stride = gridDim.x * blockDim.x;
    for (int j = i; j < GD * W0; j += stride) {
        int k = j / W0, c = j % W0;
        float v;
        if (c < 1024) { int r = c >> 7, h = c & 127; v = Wrel[((size_t)r * GD + k) * H1D + h]; }
        else          { v = Wroot[k * H1D + (c - 1024)]; }
        __half h16 = __float2half_rn(v);
        size_t b = (size_t)c * K0K;
        g_Bt0[b + k] = h16;
        g_Bt0[b + 256 + k] = h16;
    }
    // GEMM1 column order: [k | v | q | skip]
    for (int j = i; j < H1D * W1; j += stride) {
        int k = j / W1, c = j % W1;
        int seg = c >> 8, cc = c & 255;
        const float* W = (seg == 0) ? Wk : (seg == 1) ? Wv : (seg == 2) ? Wq : Ws;
        __half h16 = __float2half_rn(W[k * DD + cc]);
        size_t b = (size_t)c * K1K;
        g_Bt1[b + k] = h16;
        g_Bt1[b + 128 + k] = h16;
    }
    for (int j = i; j < W1; j += stride) {
        int seg = j >> 8, cc = j & 255;
        const float* b = (seg == 0) ? bk : (seg == 1) ? bv : (seg == 2) ? bq : bs;
        g_bqkvs[j] = b[cc];
    }
}

__global__ void gnn_convx_kernel(const float* __restrict__ x) {
    int idx = blockIdx.x * blockDim.x + threadIdx.x;
    if (idx >= NN * GD) return;
    int row = idx >> 8, col = idx & 255;
    __half h, l; split_h(x[idx], h, l);
    size_t b = (size_t)row * K0K;
    g_Ah0[b + col] = h;
    g_Ah0[b + 256 + col] = l;
}

// ---------------- counting + parallel scan + CSR fill ----------------
__global__ void gnn_count_kernel(const int* __restrict__ ei, const int* __restrict__ et) {
    int e = blockIdx.x * blockDim.x + threadIdx.x;
    if (e >= EE) return;
    int d = ei[EE + e];
    int r = et[e];
    atomicAdd(&g_cnt[r * NN + d], 1);
    atomicAdd(&g_indeg[d], 1);
}

__global__ void gnn_scanA_kernel() {
    int i = blockIdx.x * 256 + threadIdx.x;
    int v = (i < NN) ? g_indeg[i] : 0;
    __shared__ int ws[8];
    int lane = threadIdx.x & 31, wid = threadIdx.x >> 5;
    #pragma unroll
    for (int o = 16; o > 0; o >>= 1) v += __shfl_xor_sync(0xffffffffu, v, o);
    if (lane == 0) ws[wid] = v;
    __syncthreads();
    if (threadIdx.x == 0) {
        int s = 0;
        #pragma unroll
        for (int w = 0; w < 8; w++) s += ws[w];
        g_blocksum[blockIdx.x] = s;
    }
}

__global__ void gnn_scanB_kernel() {
    __shared__ int tmp[256];
    int t = threadIdx.x;
    int v = (t < NBLK) ? g_blocksum[t] : 0;
    tmp[t] = v; __syncthreads();
    for (int off = 1; off < 256; off <<= 1) {
        int a = (t >= off) ? tmp[t - off] : 0;
        __syncthreads();
        tmp[t] += a;
        __syncthreads();
    }
    if (t < NBLK) g_blockoff[t] = tmp[t] - v;
    if (t == 0) g_rowstart[0] = 0;
}

__global__ void gnn_scanC_kernel() {
    int i = blockIdx.x * 256 + threadIdx.x;
    int lane = threadIdx.x & 31, wid = threadIdx.x >> 5;
    int v = (i < NN) ? g_indeg[i] : 0;
    int x = v;
    #pragma unroll
    for (int o = 1; o < 32; o <<= 1) {
        int y = __shfl_up_sync(0xffffffffu, x, o);
        if (lane >= o) x += y;
    }
    __shared__ int wsum[8], woff[8];
    if (lane == 31) wsum[wid] = x;
    __syncthreads();
    if (threadIdx.x == 0) {
        int s = 0;
        #pragma unroll
        for (int w = 0; w < 8; w++) { woff[w] = s; s += wsum[w]; }
    }
    __syncthreads();
    int incl = x + woff[wid] + g_blockoff[blockIdx.x];
    if (i < NN) g_rowstart[i + 1] = incl;
}

__global__ void gnn_fill_kernel(const int* __restrict__ ei, const int* __restrict__ et) {
    int e = blockIdx.x * blockDim.x + threadIdx.x;
    if (e >= EE) return;
    int s = ei[e];
    int d = ei[EE + e];
    int r = et[e];
    int pos = g_rowstart[d] + atomicAdd(&g_cursor[d], 1);
    g_srcrel[pos] = s | (r << 24);
    g_ew[pos] = 1.f / (float)g_cnt[r * NN + d];
}

// ---------------- fp16 HMMA GEMM: 128x128x64 stages, 8 warps of 64x32, 3-stage cp.async ----------------
// Smem pitch = 72 halves (144B): ldmatrix 8-row group starts at banks 4r mod 32 -> distinct.
// A = [ah|al] exact fp16 pair; B = [bh|bh] duplicated -> result = x (.) bh (B-rounding error only).
#define SM_PITCH 72
#define A_SM_BYTES (128 * SM_PITCH * 2)      // 18432
#define STG_BYTES  (2 * A_SM_BYTES)          // 36864
#define GEMM_SMEM  (3 * STG_BYTES)           // 110592

template <int MODE>
__global__ void __launch_bounds__(256) hmma_gemm_kernel() {
    constexpr int KK = (MODE == 0) ? K0K : K1K;
    constexpr int SC = KK / 64;              // 8 or 4 stages
    constexpr int NC = (MODE == 0) ? W0 : W1;
    const __half* __restrict__ A = (MODE == 0) ? g_Ah0 : g_Ah1;
    const __half* __restrict__ B = (MODE == 0) ? g_Bt0 : g_Bt1;

    extern __shared__ __align__(16) char smem[];
    uint32_t sb = smem_u32(smem);
    int tid = threadIdx.x;
    int lane = tid & 31, wid = tid >> 5;
    int wm = wid >> 2, wn = wid & 3;          // 2 x 4 warps; warp tile 64 x 32
    int m0 = blockIdx.y * 128;
    int n0 = blockIdx.x * 128;

    int a_row = wm * 64 + (lane & 7) + ((lane >> 3) & 1) * 8;
    int a_k8  = (lane >= 16) ? 8 : 0;
    int b_row = wn * 32 + (lane & 7) + ((lane >= 16) ? 8 : 0);
    int b_k8  = ((lane >> 3) & 1) * 8;

    float acc[4][4][4];
    #pragma unroll
    for (int i = 0; i < 4; i++)
        #pragma unroll
        for (int j = 0; j < 4; j++)
            #pragma unroll
            for (int k = 0; k < 4; k++) acc[i][j][k] = 0.f;

    auto load_stage = [&](int sc, int st) {
        uint32_t base = sb + st * STG_BYTES;
        #pragma unroll
        for (int i = 0; i < 4; i++) {
            int idx = tid + i * 256;
            int r = idx >> 3, ch = idx & 7;
            int row = m0 + r; if (row >= NN) row = NN - 1;
            cp16(base + r * (SM_PITCH * 2) + ch * 16,
                 A + (size_t)row * KK + sc * 64 + ch * 8);
        }
        #pragma unroll
        for (int i = 0; i < 4; i++) {
            int idx = tid + i * 256;
            int r = idx >> 3, ch = idx & 7;
            cp16(base + A_SM_BYTES + r * (SM_PITCH * 2) + ch * 16,
                 B + (size_t)(n0 + r) * KK + sc * 64 + ch * 8);
        }
        CP_COMMIT();
    };

    auto compute_stage = [&](int st) {
        uint32_t aoff = sb + st * STG_BYTES;
        uint32_t boff = aoff + A_SM_BYTES;
        #pragma unroll
        for (int kk = 0; kk < 4; kk++) {
            uint32_t af[4][4];
            #pragma unroll
            for (int mf = 0; mf < 4; mf++)
                ldsm4(af[mf][0], af[mf][1], af[mf][2], af[mf][3],
                      aoff + (a_row + mf * 16) * (SM_PITCH * 2) + (kk * 16 + a_k8) * 2);
            uint32_t bf[4][2];
            #pragma unroll
            for (int jp = 0; jp < 2; jp++) {
                uint32_t r0, r1, r2, r3;
                ldsm4(r0, r1, r2, r3,
                      boff + (b_row + jp * 16) * (SM_PITCH * 2) + (kk * 16 + b_k8) * 2);
                bf[jp * 2 + 0][0] = r0; bf[jp * 2 + 0][1] = r1;
                bf[jp * 2 + 1][0] = r2; bf[jp * 2 + 1][1] = r3;
            }
            #pragma unroll
            for (int mf = 0; mf < 4; mf++)
                #pragma unroll
                for (int nf = 0; nf < 4; nf++)
                    mma16816(acc[mf][nf], af[mf][0], af[mf][1], af[mf][2], af[mf][3],
                             bf[nf][0], bf[nf][1]);
        }
    };

    load_stage(0, 0);
    load_stage(1, 1);
    for (int sc = 0; sc < SC; sc++) {
        if (sc == SC - 1) CP_WAIT0(); else CP_WAIT1();
        __syncthreads();
        if (sc + 2 < SC) load_stage(sc + 2, (sc + 2) % 3);
        compute_stage(sc % 3);
    }

    // epilogue
    int gm = m0 + wm * 64 + (lane >> 2);
    int gn0 = n0 + wn * 32 + (lane & 3) * 2;
    #pragma unroll
    for (int mf = 0; mf < 4; mf++) {
        int row = gm + mf * 16;
        #pragma unroll
        for (int nf = 0; nf < 4; nf++) {
            int col = gn0 + nf * 8;
            float c0 = acc[mf][nf][0], c1 = acc[mf][nf][1];
            float c2 = acc[mf][nf][2], c3 = acc[mf][nf][3];
            if (MODE == 0) {
                __half2 h01 = __floats2half2_rn(c0, c1);
                __half2 h23 = __floats2half2_rn(c2, c3);
                if (row < NN)     *(__half2*)(g_Y0 + (size_t)row * NC + col)       = h01;
                if (row + 8 < NN) *(__half2*)(g_Y0 + (size_t)(row + 8) * NC + col) = h23;
            } else {
                float b0 = g_bqkvs[col], b1 = g_bqkvs[col + 1];
                c0 += b0; c1 += b1; c2 += b0; c3 += b1;
                if (col < 512) {
                    __half2 h01 = __floats2half2_rn(c0, c1);
                    __half2 h23 = __floats2half2_rn(c2, c3);
                    if (row < NN)     *(__half2*)(g_kv + (size_t)row * 512 + col)       = h01;
                    if (row + 8 < NN) *(__half2*)(g_kv + (size_t)(row + 8) * 512 + col) = h23;
                } else {
                    float* dst = g_qs + (col - 512);
                    if (row < NN)     *(float2*)(dst + (size_t)row * 512)       = make_float2(c0, c1);
                    if (row + 8 < NN) *(float2*)(dst + (size_t)(row + 8) * 512) = make_float2(c2, c3);
                }
            }
        }
    }
}

// ---------------- RGCN gather: warp per dst, prefetch, fused fp16-split ----------------
__global__ void gnn_rgcn_gather_kernel(const float* __restrict__ b_rgcn) {
    int w = (int)((blockIdx.x * (size_t)blockDim.x + threadIdx.x) >> 5);
    if (w >= NN) return;
    int lane = threadIdx.x & 31;
    int h0 = lane * 4;
    float ax = 0.f, ay = 0.f, az = 0.f, aw = 0.f;
    int beg = g_rowstart[w], end = g_rowstart[w + 1];
    int sr = (beg < end) ? g_srcrel[beg] : 0;
    float wgt = (beg < end) ? g_ew[beg] : 0.f;
    for (int j = beg; j < end; j++) {
        int s = sr & 0xFFFFFF;
        int r = sr >> 24;
        float wg = wgt;
        if (j + 1 < end) { sr = g_srcrel[j + 1]; wgt = g_ew[j + 1]; }
        const __half2* yp = (const __half2*)(g_Y0 + (size_t)s * W0 + (r << 7) + h0);
        float2 f0 = __half22float2(yp[0]);
        float2 f1 = __half22float2(yp[1]);
        ax += wg * f0.x; ay += wg * f0.y; az += wg * f1.x; aw += wg * f1.y;
    }
    const __half2* rp = (const __half2*)(g_Y0 + (size_t)w * W0 + 1024 + h0);
    float2 r0 = __half22float2(rp[0]);
    float2 r1 = __half22float2(rp[1]);
    float4 bb = *(const float4*)(b_rgcn + h0);
    float o[4];
    o[0] = ax + r0.x + bb.x;
    o[1] = ay + r0.y + bb.y;
    o[2] = az + r1.x + bb.z;
    o[3] = aw + r1.y + bb.w;
    size_t base = (size_t)w * K1K;
    #pragma unroll
    for (int i = 0; i < 4; i++) {
        __half h, l; split_h(o[i], h, l);
        g_Ah1[base + h0 + i] = h;
        g_Ah1[base + 128 + h0 + i] = l;
    }
}

// ---------------- attention: warp per dst, online softmax, fused skip + BN partials ----------------
__global__ void __launch_bounds__(256) gnn_attn_kernel(float* __restrict__ out) {
    __shared__ float s_sum[DD], s_sq[DD];
    int tid = threadIdx.x;
    s_sum[tid] = 0.f; s_sq[tid] = 0.f;
    __syncthreads();

    int w = blockIdx.x * 8 + (tid >> 5);     // grid = NN/8 exactly
    int lane = tid & 31;
    int d0 = lane * 8;
    const float* qrow = g_qs + (size_t)w * 512;
    float q8[8], o8[8];
    *(float4*)&q8[0] = *(const float4*)(qrow + d0);
    *(float4*)&q8[4] = *(const float4*)(qrow + d0 + 4);
    #pragma unroll
    for (int i = 0; i < 8; i++) o8[i] = 0.f;
    float m = -3.0e38f, den = 0.f;
    int beg = g_rowstart[w], end = g_rowstart[w + 1];
    int sr = (beg < end) ? g_srcrel[beg] : 0;
    for (int j = beg; j < end; j++) {
        int s = sr & 0xFFFFFF;
        if (j + 1 < end) sr = g_srcrel[j + 1];
        const __half* kvrow = g_kv + (size_t)s * 512;
        uint4 ku = *(const uint4*)(kvrow + d0);
        uint4 vu = *(const uint4*)(kvrow + 256 + d0);
        float2 k0 = __half22float2(*(__half2*)&ku.x);
        float2 k1 = __half22float2(*(__half2*)&ku.y);
        float2 k2 = __half22float2(*(__half2*)&ku.z);
        float2 k3 = __half22float2(*(__half2*)&ku.w);
        float part = q8[0] * k0.x + q8[1] * k0.y + q8[2] * k1.x + q8[3] * k1.y
                   + q8[4] * k2.x + q8[5] * k2.y + q8[6] * k3.x + q8[7] * k3.y;
        part += __shfl_xor_sync(0xffffffffu, part, 1);
        part += __shfl_xor_sync(0xffffffffu, part, 2);
        part += __shfl_xor_sync(0xffffffffu, part, 4);
        float logit = part * 0.125f;
        float nm = fmaxf(m, logit);
        float corr = __expf(m - nm);
        float p = __expf(logit - nm);
        float2 v0 = __half22float2(*(__half2*)&vu.x);
        float2 v1 = __half22float2(*(__half2*)&vu.y);
        float2 v2 = __half22float2(*(__half2*)&vu.z);
        float2 v3 = __half22float2(*(__half2*)&vu.w);
        den = den * corr + p;
        o8[0] = o8[0] * corr + p * v0.x;
        o8[1] = o8[1] * corr + p * v0.y;
        o8[2] = o8[2] * corr + p * v1.x;
        o8[3] = o8[3] * corr + p * v1.y;
        o8[4] = o8[4] * corr + p * v2.x;
        o8[5] = o8[5] * corr + p * v2.y;
        o8[6] = o8[6] * corr + p * v3.x;
        o8[7] = o8[7] * corr + p * v3.y;
        m = nm;
    }
    float inv = (den > 0.f) ? 1.f / den : 0.f;
    float sk8[8];
    *(float4*)&sk8[0] = *(const float4*)(qrow + 256 + d0);
    *(float4*)&sk8[4] = *(const float4*)(qrow + 256 + d0 + 4);
    float r8[8];
    #pragma unroll
    for (int i = 0; i < 8; i++) r8[i] = o8[i] * inv + sk8[i];
    float* orow = out + (size_t)w * DD + d0;
    *(float4*)(orow)     = make_float4(r8[0], r8[1], r8[2], r8[3]);
    *(float4*)(orow + 4) = make_float4(r8[4], r8[5], r8[6], r8[7]);
    // BN partials
    #pragma unroll
    for (int i = 0; i < 8; i++) {
        atomicAdd(&s_sum[d0 + i], r8[i]);
        atomicAdd(&s_sq[d0 + i], r8[i] * r8[i]);
    }
    __syncthreads();
    atomicAdd(&g_bnsum[tid], s_sum[tid]);
    atomicAdd(&g_bnsumsq[tid], s_sq[tid]);
}

// ---------------- BatchNorm finalize + normalize ----------------
__global__ void gnn_bn_final_kernel(const float* __restrict__ gamma, const float* __restrict__ beta) {
    int d = threadIdx.x;
    float mu = g_bnsum[d] * (1.f / NN);
    float var = g_bnsumsq[d] * (1.f / NN) - mu * mu;
    float rstd = 1.0f / sqrtf(var + 1e-5f);
    float sc = rstd * gamma[d];
    g_scale[d] = sc;
    g_shift[d] = beta[d] - mu * sc;
}

__global__ void gnn_bn_norm_kernel(float* __restrict__ out) {
    int idx = blockIdx.x * blockDim.x + threadIdx.x;
    if (idx >= NN * DD / 4) return;
    int c = (idx * 4) & 255;
    float4 v = *(float4*)(out + (size_t)idx * 4);
    float4 y;
    y.x = v.x * g_scale[c + 0] + g_shift[c + 0];
    y.y = v.y * g_scale[c + 1] + g_shift[c + 1];
    y.z = v.z * g_scale[c + 2] + g_shift[c + 2];
    y.w = v.w * g_scale[c + 3] + g_shift[c + 3];
    y.x = (y.x >= 0.f) ? y.x : 0.01f * y.x;
    y.y = (y.y >= 0.f) ? y.y : 0.01f * y.y;
    y.z = (y.z >= 0.f) ? y.z : 0.01f * y.z;
    y.w = (y.w >= 0.f) ? y.w : 0.01f * y.w;
    *(float4*)(out + (size_t)idx * 4) = y;
}

extern "C" void kernel_launch(void* const* d_in, const int* in_sizes, int n_in,
                              void* d_out, int out_size) {
    const float* x     = (const float*)d_in[0];
    const int*   ei    = (const int*)d_in[2];
    const int*   et    = (const int*)d_in[3];
    const float* Wrel  = (const float*)d_in[4];
    const float* Wroot = (const float*)d_in[5];
    const float* brg   = (const float*)d_in[6];
    const float* Wq    = (const float*)d_in[7];
    const float* bq    = (const float*)d_in[8];
    const float* Wk    = (const float*)d_in[9];
    const float* bk    = (const float*)d_in[10];
    const float* Wv    = (const float*)d_in[11];
    const float* bv    = (const float*)d_in[12];
    const float* Ws    = (const float*)d_in[13];
    const float* bs    = (const float*)d_in[14];
    const float* gamma = (const float*)d_in[15];
    const float* beta  = (const float*)d_in[16];
    float* out = (float*)d_out;

    cudaFuncSetAttribute(hmma_gemm_kernel<0>, cudaFuncAttributeMaxDynamicSharedMemorySize, GEMM_SMEM);
    cudaFuncSetAttribute(hmma_gemm_kernel<1>, cudaFuncAttributeMaxDynamicSharedMemorySize, GEMM_SMEM);

    // Fork/join: CSR build (count/scan/fill) runs on a side stream concurrently
    // with pack/convx/GEMM0 on the main stream; they join before gather.
    // Stream/events created per call, never destroyed (kernel_launch runs only
    // for correctness + capture; graph replays do not re-enter it). No device
    // memory is allocated.
    cudaStream_t s2;
    cudaEvent_t evFork, evJoin;
    cudaStreamCreateWithFlags(&s2, cudaStreamNonBlocking);
    cudaEventCreateWithFlags(&evFork, cudaEventDisableTiming);
    cudaEventCreateWithFlags(&evJoin, cudaEventDisableTiming);

    gnn_zero_kernel<<<512, 256>>>();
    cudaEventRecord(evFork, 0);
    cudaStreamWaitEvent(s2, evFork, 0);

    // side stream: CSR build
    gnn_count_kernel<<<(EE + 255) / 256, 256, 0, s2>>>(ei, et);
    gnn_scanA_kernel<<<NBLK, 256, 0, s2>>>();
    gnn_scanB_kernel<<<1, 256, 0, s2>>>();
    gnn_scanC_kernel<<<NBLK, 256, 0, s2>>>();
    gnn_fill_kernel<<<(EE + 255) / 256, 256, 0, s2>>>(ei, et);
    cudaEventRecord(evJoin, s2);

    // main stream: pack + convert + GEMM0
    gnn_pack_kernel<<<512, 256>>>(Wrel, Wroot, Wq, Wk, Wv, Ws, bq, bk, bv, bs);
    gnn_convx_kernel<<<(NN * GD + 255) / 256, 256>>>(x);
    dim3 g0(W0 / 128, (NN + 127) / 128);
    hmma_gemm_kernel<0><<<g0, 256, GEMM_SMEM>>>();

    // join: gather needs GEMM0 (main) + CSR (side)
    cudaStreamWaitEvent(0, evJoin, 0);

    gnn_rgcn_gather_kernel<<<(NN * 32 + 255) / 256, 256>>>(brg);

    // GEMM1: [k|v|q|skip] (K=256) + bias; k|v stored fp16
    dim3 g1(W1 / 128, (NN + 127) / 128);
    hmma_gemm_kernel<1><<<g1, 256, GEMM_SMEM>>>();

    gnn_attn_kernel<<<NN / 8, 256>>>(out);

    gnn_bn_final_kernel<<<1, 256>>>(gamma, beta);
    gnn_bn_norm_kernel<<<(NN * DD / 4 + 255) / 256, 256>>>(out);
}